// round 2
// baseline (speedup 1.0000x reference)
#include <cuda_runtime.h>
#include <cuda_bf16.h>

// SEIR Euler integration.
// initial: (4, B) fp32  [S; E; I; R] rows
// beta/gamma/sigma: scalar fp32
// out: (t*B, 4) fp32, time-major: out[(n*B + b)*4 + c]
//
// Serial in time, parallel in B. One thread per region b; state in registers;
// one coalesced float4 streaming store per step. t and B are derived host-side
// from the harness contract (in_sizes[0] = 4*B, out_size = t*B*4), so no
// device-side scalar reads are needed.

__global__ void __launch_bounds__(64) seir_kernel(
    const float* __restrict__ initial,
    const float* __restrict__ beta,
    const float* __restrict__ gamma,
    const float* __restrict__ sigma,
    float4*      __restrict__ out,
    int B, int t)
{
    const int b = blockIdx.x * blockDim.x + threadIdx.x;
    if (b >= B) return;

    const float step = 0.5f;
    const float bt = beta[0];
    const float gm = gamma[0];
    const float sg = sigma[0];

    float S = initial[0 * B + b];
    float E = initial[1 * B + b];
    float I = initial[2 * B + b];
    float R = initial[3 * B + b];

    // n = 0: the initial state itself
    __stcs(&out[b], make_float4(S, E, I, R));

    int idx = b;
    #pragma unroll 4
    for (int n = 1; n < t; ++n) {
        const float bSI = bt * S * I;
        const float sE  = sg * E;
        const float gI  = gm * I;
        const float Sn = S - bSI * step;
        const float En = E + (bSI - sE) * step;
        const float In = I + (sE - gI) * step;
        const float Rn = R + gI * step;
        S = Sn; E = En; I = In; R = Rn;
        idx += B;
        __stcs(&out[idx], make_float4(S, E, I, R));
    }
}

extern "C" void kernel_launch(void* const* d_in, const int* in_sizes, int n_in,
                              void* d_out, int out_size)
{
    const float* initial = (const float*)d_in[0];   // 4*B elements
    const float* beta    = (const float*)d_in[1];
    const float* gamma   = (const float*)d_in[2];
    const float* sigma   = (const float*)d_in[3];

    const int B = in_sizes[0] / 4;
    // out_size is the element count of the (t*B, 4) fp32 output.
    const int t = (B > 0) ? (out_size / (4 * B)) : 0;

    const int block = 64;
    const int grid  = (B + block - 1) / block;
    seir_kernel<<<grid, block>>>(initial, beta, gamma, sigma,
                                 (float4*)d_out, B, t);
}

// round 5
// speedup vs baseline: 1.0153x; 1.0153x over previous
#include <cuda_runtime.h>
#include <cuda_bf16.h>

// SEIR Euler integration, two-phase checkpoint scheme with checkpoints stored
// IN-PLACE in the output (no device scratch at all).
//
// The time recurrence is serial, but compute is trivial (~10 FMA/step) while
// the output is 536 MB of pure streaming stores. Round-2 profile of the
// single-phase kernel: occ 10.5%, DRAM 61.7%, issue 18% -> latency-bound.
//
// Phase 1: B threads integrate all t steps compute-only, writing the state at
//          every CHUNK-step boundary directly to its final slot in out[].
// Phase 2: (t/CHUNK)*B threads re-load their chunk-start state from out[]
//          (L2-hot, phase 1 just wrote it) and store the remaining CHUNK-1
//          steps. ~1M threads -> stores saturate DRAM.

#define CHUNK 32

__device__ __forceinline__ float4 seir_step(float4 v, float bt, float gm, float sg)
{
    const float step = 0.5f;
    const float S = v.x, E = v.y, I = v.z, R = v.w;
    const float bSI = bt * S * I;
    const float sE  = sg * E;
    const float gI  = gm * I;
    float4 r;
    r.x = S - bSI * step;
    r.y = E + (bSI - sE) * step;
    r.z = I + (sE - gI) * step;
    r.w = R + gI * step;
    return r;
}

// ---- Phase 1: compute + store chunk-boundary states (in-place checkpoints) ----
__global__ void __launch_bounds__(128) seir_ckpt_kernel(
    const float* __restrict__ initial,
    const float* __restrict__ beta,
    const float* __restrict__ gamma,
    const float* __restrict__ sigma,
    float4* __restrict__ out,
    int B, int t)
{
    const int b = blockIdx.x * blockDim.x + threadIdx.x;
    if (b >= B) return;

    const float bt = beta[0], gm = gamma[0], sg = sigma[0];

    float4 v = make_float4(initial[0 * B + b], initial[1 * B + b],
                           initial[2 * B + b], initial[3 * B + b]);
    out[b] = v;  // state at step 0 (final position)

    const int nchunks = (t + CHUNK - 1) / CHUNK;
    for (int c = 1; c < nchunks; ++c) {
        #pragma unroll
        for (int j = 0; j < CHUNK; ++j)
            v = seir_step(v, bt, gm, sg);
        out[(size_t)c * CHUNK * B + b] = v;  // state at step c*CHUNK (final position)
    }
}

// ---- Phase 2: each thread fills in the CHUNK-1 remaining steps of one chunk ----
__global__ void __launch_bounds__(256) seir_store_kernel(
    const float* __restrict__ beta,
    const float* __restrict__ gamma,
    const float* __restrict__ sigma,
    float4* __restrict__ out,
    int B, int t)
{
    const int tid = blockIdx.x * blockDim.x + threadIdx.x;
    const int c  = tid / B;
    const int bb = tid - c * B;

    const int n0 = c * CHUNK;
    if (n0 >= t || bb >= B) return;

    const float bt = beta[0], gm = gamma[0], sg = sigma[0];

    size_t idx = (size_t)n0 * B + bb;
    float4 v = out[idx];                    // chunk-start state (written by phase 1)

    const int nlast = min(n0 + CHUNK, t);
    if (nlast == n0 + CHUNK) {
        #pragma unroll
        for (int j = 1; j < CHUNK; ++j) {
            v = seir_step(v, bt, gm, sg);
            idx += B;
            __stcs(&out[idx], v);           // state at step n0+j
        }
    } else {
        for (int n = n0 + 1; n < nlast; ++n) {
            v = seir_step(v, bt, gm, sg);
            idx += B;
            __stcs(&out[idx], v);
        }
    }
}

extern "C" void kernel_launch(void* const* d_in, const int* in_sizes, int n_in,
                              void* d_out, int out_size)
{
    const float* initial = (const float*)d_in[0];   // 4*B elements
    const float* beta    = (const float*)d_in[1];
    const float* gamma   = (const float*)d_in[2];
    const float* sigma   = (const float*)d_in[3];

    const int B = in_sizes[0] / 4;
    const int t = (B > 0) ? (out_size / (4 * B)) : 0;
    if (B <= 0 || t <= 0) return;

    const int nchunks = (t + CHUNK - 1) / CHUNK;

    // Phase 1: checkpoints straight into the output (compute-bound, ~6-8 us)
    seir_ckpt_kernel<<<(B + 127) / 128, 128>>>(initial, beta, gamma, sigma,
                                               (float4*)d_out, B, t);
    // Phase 2: parallel-in-time fill of the remaining steps (DRAM-bound)
    const long long total = (long long)nchunks * B;
    const int grid = (int)((total + 255) / 256);
    seir_store_kernel<<<grid, 256>>>(beta, gamma, sigma, (float4*)d_out, B, t);
}